// round 13
// baseline (speedup 1.0000x reference)
#include <cuda_runtime.h>
#include <math.h>

// Problem shape (fixed by reference setup_inputs)
#define N_  8192
#define M_  4096
#define D_  784
#define BM  128
#define BN  128
#define BK  16
#define NC  49           // 784 / 16 chunks
#define MTILES (M_/BN)   // 32
#define LOG_2PI 1.8378770664093453f

typedef unsigned long long u64;
typedef unsigned int u32;

// Scratch (allocation-free; referenced ONLY inside device code — never passed
// from host (that was the Round-4 bug). ~40 MB total, fits fine.)
__device__ __align__(16) float g_u[(size_t)N_ * D_];   // samples/std
__device__ __align__(16) float g_v[(size_t)M_ * D_];   // x/std
__device__ __align__(16) float g_invstd[D_];
__device__ float g_cu[N_];                 // -0.5*||u_n||^2
__device__ float g_cv[M_];                 // -0.5*||v_m||^2
__device__ float g_pmax[MTILES * N_];
__device__ float g_psum[MTILES * N_];
__device__ float g_logconst;

// ---- packed f32x2 FMA (2x fp32 throughput; proven in Round 10) -----------
__device__ __forceinline__ u64 fma2(u64 a, u64 b, u64 c) {
    u64 d;
    asm("fma.rn.f32x2 %0, %1, %2, %3;" : "=l"(d) : "l"(a), "l"(b), "l"(c));
    return d;
}
__device__ __forceinline__ float2 unpack2(u64 v) {
    float2 r;
    asm("mov.b64 {%0, %1}, %2;" : "=f"(r.x), "=f"(r.y) : "l"(v));
    return r;
}
__device__ __forceinline__ u32 smem_u32(const void* p) {
    u32 a;
    asm("{ .reg .u64 t; cvta.to.shared.u64 t, %1; cvt.u32.u64 %0, t; }"
        : "=r"(a) : "l"(p));
    return a;
}
__device__ __forceinline__ void cp_async16(u32 dst, const void* src) {
    asm volatile("cp.async.cg.shared.global [%0], [%1], 16;"
                 :: "r"(dst), "l"(src));
}
#define CP_COMMIT() asm volatile("cp.async.commit_group;" ::: "memory")
#define CP_WAIT(n)  asm volatile("cp.async.wait_group %0;" :: "n"(n) : "memory")

// ---------------------------------------------------------------------------
// invstd + logconst (proven smem-tree pattern)
__global__ __launch_bounds__(256) void prep_const(const float* __restrict__ stdv) {
    int tid = threadIdx.x;
    float s = 0.f;
    for (int d = tid; d < D_; d += 256) {
        float sv = stdv[d];
        g_invstd[d] = 1.0f / sv;
        s += logf(sv);
    }
    __shared__ float red[256];
    red[tid] = s; __syncthreads();
    #pragma unroll
    for (int k = 128; k > 0; k >>= 1) {
        if (tid < k) red[tid] += red[tid + k];
        __syncthreads();
    }
    if (tid == 0) g_logconst = -0.5f * (float)D_ * LOG_2PI - red[0];
}

// Pre-scale samples -> g_u, and g_cu = -0.5*||u||^2 (globals written directly)
__global__ __launch_bounds__(256) void prep_u(const float* __restrict__ src) {
    int r = blockIdx.x;
    int tid = threadIdx.x;
    float ss = 0.f;
    for (int d = tid; d < D_; d += 256) {
        float val = src[(size_t)r * D_ + d] * g_invstd[d];
        g_u[(size_t)r * D_ + d] = val;
        ss = fmaf(val, val, ss);
    }
    __shared__ float red[256];
    red[tid] = ss; __syncthreads();
    #pragma unroll
    for (int k = 128; k > 0; k >>= 1) {
        if (tid < k) red[tid] += red[tid + k];
        __syncthreads();
    }
    if (tid == 0) g_cu[r] = -0.5f * red[0];
}

// Pre-scale x -> g_v, and g_cv = -0.5*||v||^2
__global__ __launch_bounds__(256) void prep_v(const float* __restrict__ src) {
    int r = blockIdx.x;
    int tid = threadIdx.x;
    float ss = 0.f;
    for (int d = tid; d < D_; d += 256) {
        float val = src[(size_t)r * D_ + d] * g_invstd[d];
        g_v[(size_t)r * D_ + d] = val;
        ss = fmaf(val, val, ss);
    }
    __shared__ float red[256];
    red[tid] = ss; __syncthreads();
    #pragma unroll
    for (int k = 128; k > 0; k >>= 1) {
        if (tid < k) red[tid] += red[tid + k];
        __syncthreads();
    }
    if (tid == 0) g_cv[r] = -0.5f * red[0];
}

// ---------------------------------------------------------------------------
// Shared tiles: float4 k-quads, double-buffered for cp.async pipelining.
__shared__ float4 As4[2][4][BM];   // 16 KB
__shared__ float4 Bs4[2][4][BN];   // 16 KB
__shared__ float  redsm[BM][17];   // 8.7 KB
__shared__ float  rmx[BM];

// Issue cp.async staging of chunk c into buffer buf (A: 512 x 16B, B: same).
__device__ __forceinline__ void issue_chunk(int c, int buf, int tid,
                                            int bm, int bn,
                                            u32 smA, u32 smB) {
    #pragma unroll
    for (int t = 0; t < 2; t++) {
        int item = tid + t * 256;           // 0..511
        int r  = item >> 2;                 // row 0..127
        int k4 = item & 3;                  // k-quad 0..3
        const float* sa = g_u + (size_t)(bm * BM + r) * D_ + c * BK + k4 * 4;
        cp_async16(smA + (u32)(((buf * 4 + k4) * BM + r) * 16), sa);
        const float* sb = g_v + (size_t)(bn * BN + r) * D_ + c * BK + k4 * 4;
        cp_async16(smB + (u32)(((buf * 4 + k4) * BN + r) * 16), sb);
    }
}

// ---------------------------------------------------------------------------
// Fused dot-form kernel, pure fma2 hot loop, cp.async double-buffered.
// s[n,m] = u.v + cv[m]; per-row lse partials via proven smem reduction.
__global__ __launch_bounds__(256, 1) void dot_lse(void) {
    const int tid = threadIdx.x;
    const int tx = tid & 15;       // m direction, cols tx + 16j
    const int ty = tid >> 4;       // n direction, rows ty*8 + i
    const int bn = blockIdx.x;     // m tile 0..31
    const int bm = blockIdx.y;     // n tile 0..63

    const u32 smA = smem_u32(&As4[0][0][0]);
    const u32 smB = smem_u32(&Bs4[0][0][0]);

    u64 acc[8][8];
    #pragma unroll
    for (int i = 0; i < 8; i++)
        #pragma unroll
        for (int j = 0; j < 8; j++) acc[i][j] = 0ull;

    issue_chunk(0, 0, tid, bm, bn, smA, smB);
    CP_COMMIT();

    for (int c = 0; c < NC; c++) {
        int buf = c & 1;
        if (c + 1 < NC) {
            issue_chunk(c + 1, (c + 1) & 1, tid, bm, bn, smA, smB);
            CP_COMMIT();
            CP_WAIT(1);
        } else {
            CP_WAIT(0);
        }
        __syncthreads();

        #pragma unroll
        for (int k4 = 0; k4 < 4; k4++) {
            ulonglong2 a2[8], b2[8];
            #pragma unroll
            for (int i = 0; i < 8; i++)
                a2[i] = *(const ulonglong2*)&As4[buf][k4][ty * 8 + i];
            #pragma unroll
            for (int j = 0; j < 8; j++)
                b2[j] = *(const ulonglong2*)&Bs4[buf][k4][tx + 16 * j];
            #pragma unroll
            for (int i = 0; i < 8; i++)
                #pragma unroll
                for (int j = 0; j < 8; j++)
                    acc[i][j] = fma2(a2[i].x, b2[j].x, acc[i][j]);
            #pragma unroll
            for (int i = 0; i < 8; i++)
                #pragma unroll
                for (int j = 0; j < 8; j++)
                    acc[i][j] = fma2(a2[i].y, b2[j].y, acc[i][j]);
        }
        __syncthreads();
    }

    // ---- Epilogue ----
    float cvj[8];
    #pragma unroll
    for (int j = 0; j < 8; j++)
        cvj[j] = g_cv[bn * BN + tx + 16 * j];

    float s[8][8];
    #pragma unroll
    for (int i = 0; i < 8; i++)
        #pragma unroll
        for (int j = 0; j < 8; j++) {
            float2 t = unpack2(acc[i][j]);
            s[i][j] = (t.x + t.y) + cvj[j];
        }

    // Phase 1: per-thread row maxima, then row-wide max (proven pattern).
    #pragma unroll
    for (int i = 0; i < 8; i++) {
        float mloc = s[i][0];
        #pragma unroll
        for (int j = 1; j < 8; j++) mloc = fmaxf(mloc, s[i][j]);
        redsm[ty * 8 + i][tx] = mloc;
    }
    __syncthreads();
    if (tid < BM) {
        float rm = redsm[tid][0];
        #pragma unroll
        for (int c = 1; c < 16; c++) rm = fmaxf(rm, redsm[tid][c]);
        rmx[tid] = rm;
    }
    __syncthreads();
    // Phase 2: per-thread row sums of exp(s - rowmax), then row-wide sum.
    #pragma unroll
    for (int i = 0; i < 8; i++) {
        float rm = rmx[ty * 8 + i];
        float sloc = 0.f;
        #pragma unroll
        for (int j = 0; j < 8; j++) sloc += __expf(s[i][j] - rm);
        redsm[ty * 8 + i][tx] = sloc;
    }
    __syncthreads();
    if (tid < BM) {
        float sm = 0.f;
        #pragma unroll
        for (int c = 0; c < 16; c++) sm += redsm[tid][c];
        int row = bm * BM + tid;
        g_pmax[bn * N_ + row] = rmx[tid];
        g_psum[bn * N_ + row] = sm;
    }
}

// ---------------------------------------------------------------------------
__global__ __launch_bounds__(256) void finalize(float* __restrict__ out) {
    int n = blockIdx.x * blockDim.x + threadIdx.x;
    if (n >= N_) return;
    float gmax = -INFINITY, gsum = 0.f;
    for (int t = 0; t < MTILES; t++) {
        float mx = g_pmax[t * N_ + n];
        float s  = g_psum[t * N_ + n];
        if (mx > gmax) {
            gsum = gsum * __expf(gmax - mx) + s;
            gmax = mx;
        } else {
            gsum += s * __expf(mx - gmax);
        }
    }
    out[n] = gmax + logf(gsum) + g_cu[n] + g_logconst - logf((float)M_);
}

// ---------------------------------------------------------------------------
extern "C" void kernel_launch(void* const* d_in, const int* in_sizes, int n_in,
                              void* d_out, int out_size) {
    // Bind inputs by ELEMENT COUNT (sizes are unique)
    const float* samples = nullptr;
    const float* x       = nullptr;
    const float* stdv    = nullptr;
    for (int i = 0; i < n_in; i++) {
        if      (in_sizes[i] == N_ * D_) samples = (const float*)d_in[i];
        else if (in_sizes[i] == M_ * D_) x       = (const float*)d_in[i];
        else if (in_sizes[i] == D_)      stdv    = (const float*)d_in[i];
    }
    if (!samples || !x || !stdv) {
        samples = (const float*)d_in[0];
        x       = (const float*)d_in[1];
        stdv    = (const float*)d_in[2];
    }
    float* out = (float*)d_out;
    (void)out_size;

    prep_const<<<1, 256>>>(stdv);
    prep_u<<<N_, 256>>>(samples);
    prep_v<<<M_, 256>>>(x);
    dot_lse<<<dim3(MTILES, N_ / BM), 256>>>();
    finalize<<<(N_ + 255) / 256, 256>>>(out);
}